// round 4
// baseline (speedup 1.0000x reference)
#include <cuda_runtime.h>
#include <cstdint>

#define N_GT          128
#define CHUNK         64        // anchors per warp
#define WARPS_PER_BLK 8
#define THREADS       256
#define NBLK_MAX      512       // 262144 / (64*8)

// [gt][block] packed keys after block-level pre-reduction (512KB)
__device__ unsigned long long g_scratch[N_GT * NBLK_MAX];

// Hot loop: branch-free, division-free. Margin-certified comparisons; ambiguity
// recorded in sticky masks and resolved bit-exactly (vs jax fp32 rounding) in a
// rare epilogue pass over the smem-resident anchor chunk.
__global__ __launch_bounds__(THREADS, 4) void assign_main(
    const float4* __restrict__ anchor,
    const float4* __restrict__ gt,
    float* __restrict__ assign, int nblocks)
{
    __shared__ float4 s_anchor[WARPS_PER_BLK][CHUNK];
    __shared__ float s_gx1[N_GT], s_gy1[N_GT], s_gx2[N_GT], s_gy2[N_GT], s_ga[N_GT];
    __shared__ unsigned long long s_best[N_GT];

    const int tid  = threadIdx.x;
    const int lane = tid & 31;
    const int wid  = tid >> 5;
    const int base = (blockIdx.x * WARPS_PER_BLK + wid) * CHUNK;

    if (tid < N_GT) {
        float4 g = gt[tid];
        s_gx1[tid] = g.x; s_gy1[tid] = g.y;
        s_gx2[tid] = g.z; s_gy2[tid] = g.w;
        s_ga[tid]  = __fmul_rn(g.z - g.x, g.w - g.y);   // reference-exact area
        s_best[tid] = 0ull;
    }
    #pragma unroll
    for (int r = 0; r < CHUNK / 32; ++r)
        s_anchor[wid][r * 32 + lane] = anchor[base + r * 32 + lane];
    __syncthreads();

    float gx1[4], gy1[4], gx2[4], gy2[4], ga[4];
    float bi[4], bu[4];
    int   bidx[4];
    #pragma unroll
    for (int g = 0; g < 4; ++g) {
        int j = lane + 32 * g;
        gx1[g] = s_gx1[j]; gy1[g] = s_gy1[j];
        gx2[g] = s_gx2[j]; gy2[g] = s_gy2[j];
        ga[g]  = s_ga[j];
        bi[g] = 0.0f; bu[g] = 1.0f; bidx[g] = base;
    }

    const float c    = 0.3f;
    const float REL  = 4e-6f;      // >> fp32 quotient ulp; << top-2 gaps
    const float CROW = 1.2e-6f;    // REL * 0.3
    float myres = -1.0f;
    unsigned mlo = 0u, mhi = 0u;   // row-ambiguity bitmask over t
    int ambc = 0;                  // col-ambiguity bits per g

    #pragma unroll 2
    for (int t = 0; t < CHUNK; ++t) {
        float4 a = s_anchor[wid][t];
        float areaA = __fmul_rn(a.z - a.x, a.w - a.y);
        bool hit = false, ambt = false;

        #pragma unroll
        for (int g = 0; g < 4; ++g) {
            float w = fminf(a.z, gx2[g]) - fmaxf(a.x, gx1[g]);
            float h = fminf(a.w, gy2[g]) - fmaxf(a.y, gy1[g]);
            bool pos = (w > 0.0f) & (h > 0.0f);
            float inter = __fmul_rn(w, h);                          // ref-exact
            float u = __fadd_rn(__fadd_rn(areaA, ga[g]), -inter);   // ref-exact

            // Row: certified inter/u >= 0.3 test (margin band -> sticky mask)
            float rowv = __fmaf_rn(-c, u, inter);
            float thr2 = __fmul_rn(CROW, u);
            hit  = hit  | (pos & (rowv > thr2));
            ambt = ambt | (pos & (fabsf(rowv) <= thr2));

            // Column: certified cross-mult running argmax
            float biu  = __fmul_rn(bi[g], u);
            float d    = __fmaf_rn(inter, bu[g], -biu);
            float thrc = __fmul_rn(REL, biu);
            bool better = pos & (d > thrc);
            ambc |= (int)(pos & (fabsf(d) <= thrc)) << g;
            if (better) { bi[g] = inter; bu[g] = u; bidx[g] = base + t; }
        }

        if (ambt) { unsigned b = 1u << (t & 31); if (t < 32) mlo |= b; else mhi |= b; }
        unsigned bal = __ballot_sync(0xFFFFFFFFu, hit);
        float res = bal ? -2.0f : -1.0f;
        if ((t & 31) == lane) myres = res;
        if ((t & 31) == 31)  assign[base + (t & ~31) + lane] = myres;
    }

    // ---- Rare row fixups: exact fdiv recheck for flagged anchors ----
    unsigned wlo = __reduce_or_sync(0xFFFFFFFFu, mlo);
    unsigned whi = __reduce_or_sync(0xFFFFFFFFu, mhi);
    if (wlo | whi) {
        unsigned long long m = ((unsigned long long)whi << 32) | wlo;  // warp-uniform
        while (m) {
            int t = __ffsll(m) - 1; m &= m - 1;
            float4 a = s_anchor[wid][t];
            float areaA = __fmul_rn(a.z - a.x, a.w - a.y);
            bool h2 = false;
            #pragma unroll
            for (int g = 0; g < 4; ++g) {
                float w = fminf(a.z, gx2[g]) - fmaxf(a.x, gx1[g]);
                float h = fminf(a.w, gy2[g]) - fmaxf(a.y, gy1[g]);
                if ((w > 0.0f) & (h > 0.0f)) {
                    float inter = __fmul_rn(w, h);
                    float u = __fadd_rn(__fadd_rn(areaA, ga[g]), -inter);
                    h2 |= (__fdiv_rn(inter, u) >= c);
                }
            }
            unsigned bal = __ballot_sync(0xFFFFFFFFu, h2);
            if (lane == 0) assign[base + t] = bal ? -2.0f : -1.0f;
        }
    }

    // ---- Column keys; rare exact rescan for ambiguous (lane,g) ----
    float iou[4];
    #pragma unroll
    for (int g = 0; g < 4; ++g) iou[g] = __fdiv_rn(bi[g], bu[g]);

    if (__reduce_or_sync(0xFFFFFFFFu, (unsigned)ambc)) {
        #pragma unroll
        for (int g = 0; g < 4; ++g) {
            if ((ambc >> g) & 1) {
                float bq = 0.0f; int bix = base;   // ref iou=0 for non-overlap
                for (int t = 0; t < CHUNK; ++t) {
                    float4 a = s_anchor[wid][t];
                    float areaA = __fmul_rn(a.z - a.x, a.w - a.y);
                    float w = fminf(a.z, gx2[g]) - fmaxf(a.x, gx1[g]);
                    float h = fminf(a.w, gy2[g]) - fmaxf(a.y, gy1[g]);
                    if ((w > 0.0f) & (h > 0.0f)) {
                        float inter = __fmul_rn(w, h);
                        float u = __fadd_rn(__fadd_rn(areaA, ga[g]), -inter);
                        float q = __fdiv_rn(inter, u);
                        if (q > bq) { bq = q; bix = base + t; }  // first-wins
                    }
                }
                iou[g] = bq; bidx[g] = bix;
            }
        }
    }

    // ---- Block-level pre-reduction in shared, then one coalesced row out ----
    #pragma unroll
    for (int g = 0; g < 4; ++g) {
        int j = lane + 32 * g;
        unsigned long long key =
            ((unsigned long long)__float_as_uint(iou[g]) << 32) |
            (unsigned)(0xFFFFFFFFu - (unsigned)bidx[g]);
        atomicMax(&s_best[j], key);
    }
    __syncthreads();
    if (tid < N_GT)
        g_scratch[(size_t)tid * nblocks + blockIdx.x] = s_best[tid];
}

// Per-gt max over 512 block candidates (coalesced), then claim best anchor.
__global__ __launch_bounds__(NBLK_MAX) void reduce_cols(float* __restrict__ assign,
                                                        int nblocks, int n)
{
    const int j   = blockIdx.x;
    const int tid = threadIdx.x;

    unsigned long long best =
        (tid < nblocks) ? g_scratch[(size_t)j * nblocks + tid] : 0ull;
    #pragma unroll
    for (int o = 16; o; o >>= 1) {
        unsigned long long v = __shfl_down_sync(0xFFFFFFFFu, best, o);
        if (v > best) best = v;
    }
    __shared__ unsigned long long s[NBLK_MAX / 32];
    if ((tid & 31) == 0) s[tid >> 5] = best;
    __syncthreads();
    if (tid < 32) {
        best = (tid < NBLK_MAX / 32) ? s[tid] : 0ull;
        #pragma unroll
        for (int o = 8; o; o >>= 1) {
            unsigned long long v = __shfl_down_sync(0xFFFFFFFFu, best, o);
            if (v > best) best = v;
        }
        if (tid == 0) {
            unsigned idx = 0xFFFFFFFFu - (unsigned)(best & 0xFFFFFFFFull);
            if (idx < (unsigned)n)
                atomicMax((int*)assign + idx, __float_as_int((float)j));
        }
    }
}

extern "C" void kernel_launch(void* const* d_in, const int* in_sizes, int n_in,
                              void* d_out, int out_size) {
    int ia = (n_in >= 2 && in_sizes[1] > in_sizes[0]) ? 1 : 0;
    const float4* anchor = (const float4*)d_in[ia];
    const float4* gt     = (const float4*)d_in[1 - ia];
    float* assign = (float*)d_out;

    int n = in_sizes[ia] / 4;                              // 262144
    int nblocks = n / (CHUNK * WARPS_PER_BLK);             // 512

    assign_main<<<nblocks, THREADS>>>(anchor, gt, assign, nblocks);
    reduce_cols<<<N_GT, NBLK_MAX>>>(assign, nblocks, n);
    (void)out_size;
}